// round 9
// baseline (speedup 1.0000x reference)
#include <cuda_runtime.h>
#include <cstdint>
#include <math.h>

// ---------------------------------------------------------------------------
// Round 9: round-6 skeleton (mma.sync tf32 — tcgen05 unavailable: harness
// targets sm_103 not sm_103a) + producer-side tf32 rounding (no consumer
// cvt in attention) + rescale fused into attention tail.
// ---------------------------------------------------------------------------

constexpr int TQ  = 2048;
constexpr int TK  = 2048;
constexpr int BSZ = 4;
constexpr int CDIM = 1024;
constexpr int H   = 16;
constexpr int DH  = 64;
constexpr int BH  = BSZ * H;   // 64

__device__ __align__(16) float g_q[(size_t)BH * TQ * DH];   // tf32-rounded
__device__ __align__(16) float g_k[(size_t)BH * TK * DH];   // tf32-rounded
__device__ __align__(16) float g_v[(size_t)BH * TK * DH];   // tf32-rounded
__device__ __align__(16) float g_x[(size_t)BH * TQ * DH];

__device__ __forceinline__ unsigned f2tf(float x) {
    unsigned r; asm("cvt.rna.tf32.f32 %0, %1;" : "=r"(r) : "f"(x)); return r;
}
__device__ __forceinline__ float roundtf(float x) {
    return __uint_as_float(f2tf(x));
}
__device__ __forceinline__ void mma8(float* d, const unsigned* a, const unsigned* b) {
    asm volatile(
        "mma.sync.aligned.m16n8k8.row.col.f32.tf32.tf32.f32 "
        "{%0,%1,%2,%3},{%4,%5,%6,%7},{%8,%9},{%0,%1,%2,%3};"
        : "+f"(d[0]), "+f"(d[1]), "+f"(d[2]), "+f"(d[3])
        : "r"(a[0]), "r"(a[1]), "r"(a[2]), "r"(a[3]), "r"(b[0]), "r"(b[1]));
}
__device__ __forceinline__ unsigned sptr(const void* p) {
    return (unsigned)__cvta_generic_to_shared(p);
}
#define CP16(dst_u32, src_ptr) \
    asm volatile("cp.async.cg.shared.global [%0], [%1], 16;" :: "r"(dst_u32), "l"(src_ptr))
#define CP_COMMIT() asm volatile("cp.async.commit_group;")

// ---------------------------------------------------------------------------
// Projection GEMM core: 128x128 tile, k-step 32, double-buffered cp.async.
// Raw fp32 staged in smem; tf32 cvt at fragment load. 256 thr, 2 CTA/SM.
// ---------------------------------------------------------------------------
struct ProjSmem {
    float As[2][128 * 36];
    float Bs[2][32 * 136];
};

template<bool GATHER>
__device__ __forceinline__
void proj_body(const float* __restrict__ A, const float* __restrict__ W,
               const float* __restrict__ bias, float* __restrict__ dst,
               float scale, bool scatter, ProjSmem* sm,
               int m0, int n0)
{
    const int tid = threadIdx.x, lane = tid & 31, wid = tid >> 5;
    const int gid = lane >> 2, tig = lane & 3;
    const int wm = wid >> 2, wn = wid & 3;

    float acc[4][4][4] = {};

    auto issue = [&](int it) {
        float* AsD = sm->As[it & 1];
        float* BsD = sm->Bs[it & 1];
        const unsigned asm_ = sptr(AsD), bsm_ = sptr(BsD);
        const int k0 = it * 32;
#pragma unroll
        for (int i = 0; i < 4; i++) {
            int li = tid + i * 256;
            int r = li >> 3, c = li & 7;
            if (!GATHER) {
                CP16(asm_ + (r * 36 + c * 4) * 4, &A[(size_t)(m0 + r) * CDIM + k0 + c * 4]);
            } else {
                int m = m0 + r, t = m >> 2, b = m & 3;
                int k = k0 + c * 4, h = k >> 6, d = k & 63;
                CP16(asm_ + (r * 36 + c * 4) * 4,
                     &g_x[(((size_t)(b * H + h)) * TQ + t) * DH + d]);
            }
        }
#pragma unroll
        for (int i = 0; i < 4; i++) {
            int li = tid + i * 256;
            int r = li >> 5, c = li & 31;
            CP16(bsm_ + (r * 136 + c * 4) * 4, &W[(size_t)(k0 + r) * CDIM + n0 + c * 4]);
        }
        CP_COMMIT();
    };

    issue(0);

    for (int it = 0; it < 32; it++) {
        if (it < 31) issue(it + 1);
        if (it < 31) asm volatile("cp.async.wait_group 1;");
        else         asm volatile("cp.async.wait_group 0;");
        __syncthreads();

        const float* AsF = sm->As[it & 1];
        const float* BsF = sm->Bs[it & 1];

#pragma unroll
        for (int kk = 0; kk < 32; kk += 8) {
            unsigned af[4][4], bf[4][2];
#pragma unroll
            for (int mi = 0; mi < 4; mi++) {
                int rb = wm * 64 + mi * 16;
                af[mi][0] = f2tf(AsF[(rb + gid)     * 36 + kk + tig]);
                af[mi][1] = f2tf(AsF[(rb + gid + 8) * 36 + kk + tig]);
                af[mi][2] = f2tf(AsF[(rb + gid)     * 36 + kk + tig + 4]);
                af[mi][3] = f2tf(AsF[(rb + gid + 8) * 36 + kk + tig + 4]);
            }
#pragma unroll
            for (int ni = 0; ni < 4; ni++) {
                int cb = wn * 32 + ni * 8;
                bf[ni][0] = f2tf(BsF[(kk + tig)     * 136 + cb + gid]);
                bf[ni][1] = f2tf(BsF[(kk + tig + 4) * 136 + cb + gid]);
            }
#pragma unroll
            for (int mi = 0; mi < 4; mi++)
#pragma unroll
                for (int ni = 0; ni < 4; ni++) mma8(acc[mi][ni], af[mi], bf[ni]);
        }
        __syncthreads();
    }

#pragma unroll
    for (int mi = 0; mi < 4; mi++)
#pragma unroll
        for (int hl = 0; hl < 2; hl++) {
            int m = m0 + wm * 64 + mi * 16 + gid + hl * 8;
#pragma unroll
            for (int ni = 0; ni < 4; ni++) {
                int n = n0 + wn * 32 + ni * 8 + tig * 2;
                float2 v;
                v.x = (acc[mi][ni][hl * 2 + 0] + bias[n + 0]) * scale;
                v.y = (acc[mi][ni][hl * 2 + 1] + bias[n + 1]) * scale;
                if (scatter) {
                    // producer-side tf32 rounding: attention consumes raw bits
                    v.x = roundtf(v.x); v.y = roundtf(v.y);
                    int t = m >> 2, b = m & 3, h = n >> 6, d = n & 63;
                    *(float2*)&dst[(((size_t)(b * H + h)) * TQ + t) * DH + d] = v;
                } else {
                    *(float2*)&dst[(size_t)m * CDIM + n] = v;
                }
            }
        }
}

__global__ __launch_bounds__(256, 2)
void qkv_proj_kernel(const float* __restrict__ Aq, const float* __restrict__ Ak,
                     const float* __restrict__ Av,
                     const float* __restrict__ Wq, const float* __restrict__ Wk,
                     const float* __restrict__ Wv,
                     const float* __restrict__ bq, const float* __restrict__ bk,
                     const float* __restrict__ bv)
{
    extern __shared__ char smraw[];
    ProjSmem* sm = (ProjSmem*)smraw;
    const int z = blockIdx.z;
    const float* A    = (z == 0) ? Aq : (z == 1) ? Ak : Av;
    const float* W    = (z == 0) ? Wq : (z == 1) ? Wk : Wv;
    const float* bias = (z == 0) ? bq : (z == 1) ? bk : bv;
    float* dst        = (z == 0) ? g_q : (z == 1) ? g_k : g_v;
    const float scale = (z == 0) ? 0.125f : 1.f;
    proj_body<false>(A, W, bias, dst, scale, true, sm,
                     blockIdx.y * 128, blockIdx.x * 128);
}

__global__ __launch_bounds__(256, 2)
void out_proj_kernel(const float* __restrict__ W, const float* __restrict__ bias,
                     float* __restrict__ Out)
{
    extern __shared__ char smraw[];
    ProjSmem* sm = (ProjSmem*)smraw;
    proj_body<true>(nullptr, W, bias, Out, 1.f, false, sm,
                    blockIdx.y * 128, blockIdx.x * 128);
}

constexpr int PROJ_SMEM = sizeof(ProjSmem);   // 71.7 KB

// ---------------------------------------------------------------------------
// attn_fused (512 threads, 16 warps): operands pre-rounded tf32 -> no cvt on
// Q/K/V fragments. Per key tile: S=QK^T, E=exp(S+mask) -> attn unnormalized
// + rowsum + Ps tf32-perm, O += E@V. Tail: 1/l, O*=inv -> g_x (rounded for
// out_proj), fused attn rescale over this CTA's 128 rows.
// smem u32 map: Qs 0..8704 | Ks[2] 8704..26112 | Vs 26112..34816 |
//   Ps 34816..51712 | mskAll 51712..53760 | red 53760..54272 | sm_inv ..54400
// ---------------------------------------------------------------------------
constexpr int AT_SMEM = 54400 * 4;   // 217.6 KB

__global__ __launch_bounds__(512, 1)
void attn_fused_kernel(const unsigned char* __restrict__ mask,
                       float* __restrict__ attn)
{
    extern __shared__ unsigned smem_u[];
    unsigned* Qs  = smem_u;                        // [128][68] perm tf32
    unsigned* Ks0 = smem_u + 8704;                 // [n:128][d:64] s68 tf32 bits
    unsigned* Ks1 = smem_u + 17408;
    unsigned* Vs  = smem_u + 26112;                // [n:128][d:64] s68 tf32 bits
    unsigned* Ps  = smem_u + 34816;                // [128][132] tf32 perm
    float* mskAll = (float*)(smem_u + 51712);      // [2048]
    float* red    = (float*)(smem_u + 53760);      // [4][128]
    float* sm_inv = (float*)(smem_u + 54272);

    const int tid = threadIdx.x, lane = tid & 31, wid = tid >> 5;
    const int gid = lane >> 2, tig = lane & 3;
    const int wm = wid >> 2, wn = wid & 3;         // 4 x 4 warps
    const int m0 = blockIdx.x * 128, bh = blockIdx.y, b = bh >> 4;

    const float* kbase = g_k + (size_t)bh * TK * DH;
    const float* vbase = g_v + (size_t)bh * TK * DH;

    // Q -> smem (already tf32-rounded), permuted cols
#pragma unroll
    for (int i = 0; i < 4; i++) {
        int li = tid + i * 512;
        int r = li >> 4, c = li & 15;
        uint4 a = *(const uint4*)&g_q[((size_t)bh * TQ + m0 + r) * DH + c * 4];
        unsigned* q = &Qs[r * 68 + (c >> 1) * 8 + (c & 1)];
        q[0] = a.x; q[2] = a.y; q[4] = a.z; q[6] = a.w;
    }
#pragma unroll
    for (int i = 0; i < 4; i++) {
        int idx = tid + i * 512;
        mskAll[idx] = mask[(size_t)b * TK + idx] ? -INFINITY : 0.f;
    }
    {
        const unsigned ksm = sptr(Ks0);
#pragma unroll
        for (int j = 0; j < 4; j++) {
            int li = tid + j * 512;
            int r = li >> 4, c16 = li & 15;
            CP16(ksm + (r * 68 + c16 * 4) * 4, kbase + r * 64 + c16 * 4);
        }
        CP_COMMIT();
    }

    float acco[2][2][4] = {};
    float lsum[2][2] = {};
    const int perm0 = ((2 * tig) & 3) * 2 + (tig >> 1);

    for (int nt = 0; nt < 16; nt++) {
        const int n0 = nt * 128;
        __syncthreads();

        {
            const unsigned vsm = sptr(Vs);
#pragma unroll
            for (int j = 0; j < 4; j++) {
                int li = tid + j * 512;
                int r = li >> 4, c16 = li & 15;
                CP16(vsm + (r * 68 + c16 * 4) * 4, vbase + (size_t)(n0 + r) * 64 + c16 * 4);
            }
            CP_COMMIT();
        }
        if (nt < 15) {
            unsigned* Kn = ((nt + 1) & 1) ? Ks1 : Ks0;
            const unsigned ksm = sptr(Kn);
#pragma unroll
            for (int j = 0; j < 4; j++) {
                int li = tid + j * 512;
                int r = li >> 4, c16 = li & 15;
                CP16(ksm + (r * 68 + c16 * 4) * 4,
                     kbase + (size_t)(n0 + 128 + r) * 64 + c16 * 4);
            }
            CP_COMMIT();
        }

        if (nt < 15) asm volatile("cp.async.wait_group 2;");
        else         asm volatile("cp.async.wait_group 1;");
        __syncthreads();

        const unsigned* Ksu = (nt & 1) ? Ks1 : Ks0;

        // S = Q @ K^T (no cvt: operands are pre-rounded tf32 bits)
        float acc[2][4][4] = {};
#pragma unroll
        for (int kk = 0; kk < 64; kk += 8) {
            unsigned af[2][4], bf[4][2];
#pragma unroll
            for (int mi = 0; mi < 2; mi++) {
                int rb = wm * 32 + mi * 16;
                uint2 lo = *(const uint2*)&Qs[(rb + gid)     * 68 + kk + tig * 2];
                uint2 hi = *(const uint2*)&Qs[(rb + gid + 8) * 68 + kk + tig * 2];
                af[mi][0] = lo.x; af[mi][1] = hi.x; af[mi][2] = lo.y; af[mi][3] = hi.y;
            }
#pragma unroll
            for (int ni = 0; ni < 4; ni++) {
                int cb = wn * 32 + ni * 8;
                bf[ni][0] = Ksu[(cb + gid) * 68 + kk + tig];
                bf[ni][1] = Ksu[(cb + gid) * 68 + kk + tig + 4];
            }
#pragma unroll
            for (int mi = 0; mi < 2; mi++)
#pragma unroll
                for (int ni = 0; ni < 4; ni++) mma8(acc[mi][ni], af[mi], bf[ni]);
        }

        float mk[4][2];
#pragma unroll
        for (int ni = 0; ni < 4; ni++) {
            float2 mm = *(const float2*)&mskAll[n0 + wn * 32 + ni * 8 + 2 * tig];
            mk[ni][0] = mm.x; mk[ni][1] = mm.y;
        }

        // E = exp(S+mask): attn write (unnormalized), rowsum, Ps stage
#pragma unroll
        for (int mi = 0; mi < 2; mi++) {
            int rb = wm * 32 + mi * 16;
#pragma unroll
            for (int hl = 0; hl < 2; hl++) {
                int row = rb + gid + hl * 8;
                float* arow = attn + ((size_t)bh * TQ + m0 + row) * TK + n0;
                float ls = 0.f;
#pragma unroll
                for (int ni = 0; ni < 4; ni++) {
                    int cb = wn * 32 + ni * 8;
                    float p0 = __expf(acc[mi][ni][hl * 2]     + mk[ni][0]);
                    float p1 = __expf(acc[mi][ni][hl * 2 + 1] + mk[ni][1]);
                    *(float2*)&arow[cb + 2 * tig] = make_float2(p0, p1);
                    unsigned* pp = &Ps[row * 132 + cb + perm0];
                    pp[0] = f2tf(p0); pp[2] = f2tf(p1);
                    ls += p0 + p1;
                }
                lsum[mi][hl] += ls;
            }
        }

        if (nt < 15) asm volatile("cp.async.wait_group 1;");
        else         asm volatile("cp.async.wait_group 0;");
        __syncthreads();

        // O += E @ V   (no cvt on V fragments)
#pragma unroll
        for (int kk = 0; kk < 128; kk += 8) {
            unsigned af[2][4], bf[2][2];
#pragma unroll
            for (int mi = 0; mi < 2; mi++) {
                int rb = wm * 32 + mi * 16;
                uint2 lo = *(const uint2*)&Ps[(rb + gid)     * 132 + kk + tig * 2];
                uint2 hi = *(const uint2*)&Ps[(rb + gid + 8) * 132 + kk + tig * 2];
                af[mi][0] = lo.x; af[mi][1] = hi.x; af[mi][2] = lo.y; af[mi][3] = hi.y;
            }
#pragma unroll
            for (int ni = 0; ni < 2; ni++) {
                int cb = wn * 16 + ni * 8;
                bf[ni][0] = Vs[(kk + tig)     * 68 + cb + gid];
                bf[ni][1] = Vs[(kk + tig + 4) * 68 + cb + gid];
            }
#pragma unroll
            for (int mi = 0; mi < 2; mi++)
#pragma unroll
                for (int ni = 0; ni < 2; ni++) mma8(acco[mi][ni], af[mi], bf[ni]);
        }
    }

    // rowsum -> 1/l
    __syncthreads();
#pragma unroll
    for (int mi = 0; mi < 2; mi++)
#pragma unroll
        for (int hl = 0; hl < 2; hl++) {
            float v = lsum[mi][hl];
            v += __shfl_xor_sync(~0u, v, 1);
            v += __shfl_xor_sync(~0u, v, 2);
            if (tig == 0) red[wn * 128 + wm * 32 + mi * 16 + gid + hl * 8] = v;
        }
    __syncthreads();
    if (tid < 128)
        sm_inv[tid] = 1.f / (red[tid] + red[128 + tid] + red[256 + tid] + red[384 + tid]);
    __syncthreads();

    // O normalize (+ tf32 round so out_proj A-cvt is identity) -> g_x
#pragma unroll
    for (int mi = 0; mi < 2; mi++)
#pragma unroll
        for (int hl = 0; hl < 2; hl++) {
            int row = wm * 32 + mi * 16 + gid + hl * 8;
            float inv = sm_inv[row];
#pragma unroll
            for (int ni = 0; ni < 2; ni++) {
                int c = wn * 16 + ni * 8 + tig * 2;
                *(float2*)&g_x[((size_t)bh * TQ + m0 + row) * DH + c] =
                    make_float2(acco[mi][ni][hl * 2] * inv,
                                acco[mi][ni][hl * 2 + 1] * inv);
            }
        }

    // fused rescale of this CTA's 128 attn rows (overlaps other CTAs' mma)
    float4* ab = (float4*)(attn + ((size_t)bh * TQ + m0) * TK);
    for (int r = 0; r < 128; r++) {
        const float inv = sm_inv[r];
        float4 v = ab[(size_t)r * 512 + tid];
        v.x *= inv; v.y *= inv; v.z *= inv; v.w *= inv;
        ab[(size_t)r * 512 + tid] = v;
    }
}

// ---------------------------------------------------------------------------
extern "C" void kernel_launch(void* const* d_in, const int* in_sizes, int n_in,
                              void* d_out, int out_size)
{
    const float* query = (const float*)d_in[0];
    const float* key   = (const float*)d_in[1];
    const float* value = (const float*)d_in[2];
    const unsigned char* mask = (const unsigned char*)d_in[3];
    const float* Wq = (const float*)d_in[4];
    const float* bq = (const float*)d_in[5];
    const float* Wk = (const float*)d_in[6];
    const float* bk = (const float*)d_in[7];
    const float* Wv = (const float*)d_in[8];
    const float* bv = (const float*)d_in[9];
    const float* Wo = (const float*)d_in[10];
    const float* bo = (const float*)d_in[11];

    float* out_x = (float*)d_out;                       // [2048,4,1024]
    float* attn  = out_x + (size_t)TQ * BSZ * CDIM;     // [64,2048,2048]

    cudaFuncSetAttribute(attn_fused_kernel,
                         cudaFuncAttributeMaxDynamicSharedMemorySize, AT_SMEM);
    cudaFuncSetAttribute(qkv_proj_kernel,
                         cudaFuncAttributeMaxDynamicSharedMemorySize, PROJ_SMEM);
    cudaFuncSetAttribute(out_proj_kernel,
                         cudaFuncAttributeMaxDynamicSharedMemorySize, PROJ_SMEM);

    qkv_proj_kernel<<<dim3(8, 64, 3), 256, PROJ_SMEM>>>(query, key, value,
                                                        Wq, Wk, Wv, bq, bk, bv);
    attn_fused_kernel<<<dim3(16, 64), 512, AT_SMEM>>>(mask, attn);
    out_proj_kernel<<<dim3(8, 64), 256, PROJ_SMEM>>>(Wo, bo, out_x);
}

// round 10
// speedup vs baseline: 1.0138x; 1.0138x over previous
#include <cuda_runtime.h>
#include <cstdint>
#include <math.h>

// ---------------------------------------------------------------------------
// Round 10: round-9 base, but rescale moved OUT of attn tail and co-scheduled
// with out_proj in one heterogeneous launch (tensor-bound + HBM-bound mix).
// ---------------------------------------------------------------------------

constexpr int TQ  = 2048;
constexpr int TK  = 2048;
constexpr int BSZ = 4;
constexpr int CDIM = 1024;
constexpr int H   = 16;
constexpr int DH  = 64;
constexpr int BH  = BSZ * H;   // 64

__device__ __align__(16) float g_q[(size_t)BH * TQ * DH];   // tf32-rounded
__device__ __align__(16) float g_k[(size_t)BH * TK * DH];   // tf32-rounded
__device__ __align__(16) float g_v[(size_t)BH * TK * DH];   // tf32-rounded
__device__ __align__(16) float g_x[(size_t)BH * TQ * DH];
__device__ float g_linv[(size_t)BH * TQ];

__device__ __forceinline__ unsigned f2tf(float x) {
    unsigned r; asm("cvt.rna.tf32.f32 %0, %1;" : "=r"(r) : "f"(x)); return r;
}
__device__ __forceinline__ float roundtf(float x) {
    return __uint_as_float(f2tf(x));
}
__device__ __forceinline__ void mma8(float* d, const unsigned* a, const unsigned* b) {
    asm volatile(
        "mma.sync.aligned.m16n8k8.row.col.f32.tf32.tf32.f32 "
        "{%0,%1,%2,%3},{%4,%5,%6,%7},{%8,%9},{%0,%1,%2,%3};"
        : "+f"(d[0]), "+f"(d[1]), "+f"(d[2]), "+f"(d[3])
        : "r"(a[0]), "r"(a[1]), "r"(a[2]), "r"(a[3]), "r"(b[0]), "r"(b[1]));
}
__device__ __forceinline__ unsigned sptr(const void* p) {
    return (unsigned)__cvta_generic_to_shared(p);
}
#define CP16(dst_u32, src_ptr) \
    asm volatile("cp.async.cg.shared.global [%0], [%1], 16;" :: "r"(dst_u32), "l"(src_ptr))
#define CP_COMMIT() asm volatile("cp.async.commit_group;")

// ---------------------------------------------------------------------------
// Projection GEMM core: 128x128 tile, k-step 32, double-buffered cp.async.
// ---------------------------------------------------------------------------
struct ProjSmem {
    float As[2][128 * 36];
    float Bs[2][32 * 136];
};

template<bool GATHER>
__device__ __forceinline__
void proj_body(const float* __restrict__ A, const float* __restrict__ W,
               const float* __restrict__ bias, float* __restrict__ dst,
               float scale, bool scatter, ProjSmem* sm,
               int m0, int n0)
{
    const int tid = threadIdx.x, lane = tid & 31, wid = tid >> 5;
    const int gid = lane >> 2, tig = lane & 3;
    const int wm = wid >> 2, wn = wid & 3;

    float acc[4][4][4] = {};

    auto issue = [&](int it) {
        float* AsD = sm->As[it & 1];
        float* BsD = sm->Bs[it & 1];
        const unsigned asm_ = sptr(AsD), bsm_ = sptr(BsD);
        const int k0 = it * 32;
#pragma unroll
        for (int i = 0; i < 4; i++) {
            int li = tid + i * 256;
            int r = li >> 3, c = li & 7;
            if (!GATHER) {
                CP16(asm_ + (r * 36 + c * 4) * 4, &A[(size_t)(m0 + r) * CDIM + k0 + c * 4]);
            } else {
                int m = m0 + r, t = m >> 2, b = m & 3;
                int k = k0 + c * 4, h = k >> 6, d = k & 63;
                CP16(asm_ + (r * 36 + c * 4) * 4,
                     &g_x[(((size_t)(b * H + h)) * TQ + t) * DH + d]);
            }
        }
#pragma unroll
        for (int i = 0; i < 4; i++) {
            int li = tid + i * 256;
            int r = li >> 5, c = li & 31;
            CP16(bsm_ + (r * 136 + c * 4) * 4, &W[(size_t)(k0 + r) * CDIM + n0 + c * 4]);
        }
        CP_COMMIT();
    };

    issue(0);

    for (int it = 0; it < 32; it++) {
        if (it < 31) issue(it + 1);
        if (it < 31) asm volatile("cp.async.wait_group 1;");
        else         asm volatile("cp.async.wait_group 0;");
        __syncthreads();

        const float* AsF = sm->As[it & 1];
        const float* BsF = sm->Bs[it & 1];

#pragma unroll
        for (int kk = 0; kk < 32; kk += 8) {
            unsigned af[4][4], bf[4][2];
#pragma unroll
            for (int mi = 0; mi < 4; mi++) {
                int rb = wm * 64 + mi * 16;
                af[mi][0] = f2tf(AsF[(rb + gid)     * 36 + kk + tig]);
                af[mi][1] = f2tf(AsF[(rb + gid + 8) * 36 + kk + tig]);
                af[mi][2] = f2tf(AsF[(rb + gid)     * 36 + kk + tig + 4]);
                af[mi][3] = f2tf(AsF[(rb + gid + 8) * 36 + kk + tig + 4]);
            }
#pragma unroll
            for (int ni = 0; ni < 4; ni++) {
                int cb = wn * 32 + ni * 8;
                bf[ni][0] = f2tf(BsF[(kk + tig)     * 136 + cb + gid]);
                bf[ni][1] = f2tf(BsF[(kk + tig + 4) * 136 + cb + gid]);
            }
#pragma unroll
            for (int mi = 0; mi < 4; mi++)
#pragma unroll
                for (int ni = 0; ni < 4; ni++) mma8(acc[mi][ni], af[mi], bf[ni]);
        }
        __syncthreads();
    }

#pragma unroll
    for (int mi = 0; mi < 4; mi++)
#pragma unroll
        for (int hl = 0; hl < 2; hl++) {
            int m = m0 + wm * 64 + mi * 16 + gid + hl * 8;
#pragma unroll
            for (int ni = 0; ni < 4; ni++) {
                int n = n0 + wn * 32 + ni * 8 + tig * 2;
                float2 v;
                v.x = (acc[mi][ni][hl * 2 + 0] + bias[n + 0]) * scale;
                v.y = (acc[mi][ni][hl * 2 + 1] + bias[n + 1]) * scale;
                if (scatter) {
                    v.x = roundtf(v.x); v.y = roundtf(v.y);
                    int t = m >> 2, b = m & 3, h = n >> 6, d = n & 63;
                    *(float2*)&dst[(((size_t)(b * H + h)) * TQ + t) * DH + d] = v;
                } else {
                    *(float2*)&dst[(size_t)m * CDIM + n] = v;
                }
            }
        }
}

__global__ __launch_bounds__(256, 2)
void qkv_proj_kernel(const float* __restrict__ Aq, const float* __restrict__ Ak,
                     const float* __restrict__ Av,
                     const float* __restrict__ Wq, const float* __restrict__ Wk,
                     const float* __restrict__ Wv,
                     const float* __restrict__ bq, const float* __restrict__ bk,
                     const float* __restrict__ bv)
{
    extern __shared__ char smraw[];
    ProjSmem* sm = (ProjSmem*)smraw;
    const int z = blockIdx.z;
    const float* A    = (z == 0) ? Aq : (z == 1) ? Ak : Av;
    const float* W    = (z == 0) ? Wq : (z == 1) ? Wk : Wv;
    const float* bias = (z == 0) ? bq : (z == 1) ? bk : bv;
    float* dst        = (z == 0) ? g_q : (z == 1) ? g_k : g_v;
    const float scale = (z == 0) ? 0.125f : 1.f;
    proj_body<false>(A, W, bias, dst, scale, true, sm,
                     blockIdx.y * 128, blockIdx.x * 128);
}

constexpr int PROJ_SMEM = sizeof(ProjSmem);   // 71.7 KB

// ---------------------------------------------------------------------------
// Heterogeneous epilogue: every 33rd block is an out_proj 128x128 tile
// (512 tiles), the other 32/33 are attn-rescale blocks (16384 x 8 rows).
// Tensor-bound and HBM-bound blocks co-schedule on the same waves.
// ---------------------------------------------------------------------------
__global__ __launch_bounds__(256, 2)
void epilogue_kernel(const float* __restrict__ W, const float* __restrict__ bias,
                     float* __restrict__ Out, float* __restrict__ attn)
{
    const int g = blockIdx.x;
    const int p = g / 33, r = g % 33;
    if (r == 0) {
        // out_proj tile p: bx = p & 7 (n-tile), by = p >> 3 (m-tile)
        extern __shared__ char smraw[];
        ProjSmem* sm = (ProjSmem*)smraw;
        proj_body<true>(nullptr, W, bias, Out, 1.f, false, sm,
                        (p >> 3) * 128, (p & 7) * 128);
    } else {
        // rescale block: 8 rows of attn
        const size_t row0 = ((size_t)p * 32 + (r - 1)) * 8;
        const int tid = threadIdx.x;
#pragma unroll
        for (int rr = 0; rr < 8; rr++) {
            const size_t row = row0 + rr;
            const float inv = g_linv[row];
            float4* pr = (float4*)(attn + row * (size_t)TK);
            float4 v0 = pr[tid], v1 = pr[tid + 256];
            v0.x *= inv; v0.y *= inv; v0.z *= inv; v0.w *= inv;
            v1.x *= inv; v1.y *= inv; v1.z *= inv; v1.w *= inv;
            pr[tid] = v0; pr[tid + 256] = v1;
        }
    }
}

// ---------------------------------------------------------------------------
// attn_fused (512 threads, 16 warps): S=QK^T, E=exp(S+mask) -> attn
// unnormalized + rowsum + Ps tf32-perm, O += E@V. Tail: 1/l -> g_linv,
// O*=inv -> g_x. (Rescale handled by epilogue_kernel.)
// ---------------------------------------------------------------------------
constexpr int AT_SMEM = 54400 * 4;   // 217.6 KB

__global__ __launch_bounds__(512, 1)
void attn_fused_kernel(const unsigned char* __restrict__ mask,
                       float* __restrict__ attn)
{
    extern __shared__ unsigned smem_u[];
    unsigned* Qs  = smem_u;                        // [128][68] perm tf32
    unsigned* Ks0 = smem_u + 8704;                 // [n:128][d:64] s68 tf32 bits
    unsigned* Ks1 = smem_u + 17408;
    unsigned* Vs  = smem_u + 26112;                // [n:128][d:64] s68 tf32 bits
    unsigned* Ps  = smem_u + 34816;                // [128][132] tf32 perm
    float* mskAll = (float*)(smem_u + 51712);      // [2048]
    float* red    = (float*)(smem_u + 53760);      // [4][128]
    float* sm_inv = (float*)(smem_u + 54272);

    const int tid = threadIdx.x, lane = tid & 31, wid = tid >> 5;
    const int gid = lane >> 2, tig = lane & 3;
    const int wm = wid >> 2, wn = wid & 3;         // 4 x 4 warps
    const int m0 = blockIdx.x * 128, bh = blockIdx.y, b = bh >> 4;

    const float* kbase = g_k + (size_t)bh * TK * DH;
    const float* vbase = g_v + (size_t)bh * TK * DH;

#pragma unroll
    for (int i = 0; i < 4; i++) {
        int li = tid + i * 512;
        int r = li >> 4, c = li & 15;
        uint4 a = *(const uint4*)&g_q[((size_t)bh * TQ + m0 + r) * DH + c * 4];
        unsigned* q = &Qs[r * 68 + (c >> 1) * 8 + (c & 1)];
        q[0] = a.x; q[2] = a.y; q[4] = a.z; q[6] = a.w;
    }
#pragma unroll
    for (int i = 0; i < 4; i++) {
        int idx = tid + i * 512;
        mskAll[idx] = mask[(size_t)b * TK + idx] ? -INFINITY : 0.f;
    }
    {
        const unsigned ksm = sptr(Ks0);
#pragma unroll
        for (int j = 0; j < 4; j++) {
            int li = tid + j * 512;
            int r = li >> 4, c16 = li & 15;
            CP16(ksm + (r * 68 + c16 * 4) * 4, kbase + r * 64 + c16 * 4);
        }
        CP_COMMIT();
    }

    float acco[2][2][4] = {};
    float lsum[2][2] = {};
    const int perm0 = ((2 * tig) & 3) * 2 + (tig >> 1);

    for (int nt = 0; nt < 16; nt++) {
        const int n0 = nt * 128;
        __syncthreads();

        {
            const unsigned vsm = sptr(Vs);
#pragma unroll
            for (int j = 0; j < 4; j++) {
                int li = tid + j * 512;
                int r = li >> 4, c16 = li & 15;
                CP16(vsm + (r * 68 + c16 * 4) * 4, vbase + (size_t)(n0 + r) * 64 + c16 * 4);
            }
            CP_COMMIT();
        }
        if (nt < 15) {
            unsigned* Kn = ((nt + 1) & 1) ? Ks1 : Ks0;
            const unsigned ksm = sptr(Kn);
#pragma unroll
            for (int j = 0; j < 4; j++) {
                int li = tid + j * 512;
                int r = li >> 4, c16 = li & 15;
                CP16(ksm + (r * 68 + c16 * 4) * 4,
                     kbase + (size_t)(n0 + 128 + r) * 64 + c16 * 4);
            }
            CP_COMMIT();
        }

        if (nt < 15) asm volatile("cp.async.wait_group 2;");
        else         asm volatile("cp.async.wait_group 1;");
        __syncthreads();

        const unsigned* Ksu = (nt & 1) ? Ks1 : Ks0;

        // S = Q @ K^T
        float acc[2][4][4] = {};
#pragma unroll
        for (int kk = 0; kk < 64; kk += 8) {
            unsigned af[2][4], bf[4][2];
#pragma unroll
            for (int mi = 0; mi < 2; mi++) {
                int rb = wm * 32 + mi * 16;
                uint2 lo = *(const uint2*)&Qs[(rb + gid)     * 68 + kk + tig * 2];
                uint2 hi = *(const uint2*)&Qs[(rb + gid + 8) * 68 + kk + tig * 2];
                af[mi][0] = lo.x; af[mi][1] = hi.x; af[mi][2] = lo.y; af[mi][3] = hi.y;
            }
#pragma unroll
            for (int ni = 0; ni < 4; ni++) {
                int cb = wn * 32 + ni * 8;
                bf[ni][0] = Ksu[(cb + gid) * 68 + kk + tig];
                bf[ni][1] = Ksu[(cb + gid) * 68 + kk + tig + 4];
            }
#pragma unroll
            for (int mi = 0; mi < 2; mi++)
#pragma unroll
                for (int ni = 0; ni < 4; ni++) mma8(acc[mi][ni], af[mi], bf[ni]);
        }

        float mk[4][2];
#pragma unroll
        for (int ni = 0; ni < 4; ni++) {
            float2 mm = *(const float2*)&mskAll[n0 + wn * 32 + ni * 8 + 2 * tig];
            mk[ni][0] = mm.x; mk[ni][1] = mm.y;
        }

        // E = exp(S+mask): attn write (unnormalized), rowsum, Ps stage
#pragma unroll
        for (int mi = 0; mi < 2; mi++) {
            int rb = wm * 32 + mi * 16;
#pragma unroll
            for (int hl = 0; hl < 2; hl++) {
                int row = rb + gid + hl * 8;
                float* arow = attn + ((size_t)bh * TQ + m0 + row) * TK + n0;
                float ls = 0.f;
#pragma unroll
                for (int ni = 0; ni < 4; ni++) {
                    int cb = wn * 32 + ni * 8;
                    float p0 = __expf(acc[mi][ni][hl * 2]     + mk[ni][0]);
                    float p1 = __expf(acc[mi][ni][hl * 2 + 1] + mk[ni][1]);
                    *(float2*)&arow[cb + 2 * tig] = make_float2(p0, p1);
                    unsigned* pp = &Ps[row * 132 + cb + perm0];
                    pp[0] = f2tf(p0); pp[2] = f2tf(p1);
                    ls += p0 + p1;
                }
                lsum[mi][hl] += ls;
            }
        }

        if (nt < 15) asm volatile("cp.async.wait_group 1;");
        else         asm volatile("cp.async.wait_group 0;");
        __syncthreads();

        // O += E @ V
#pragma unroll
        for (int kk = 0; kk < 128; kk += 8) {
            unsigned af[2][4], bf[2][2];
#pragma unroll
            for (int mi = 0; mi < 2; mi++) {
                int rb = wm * 32 + mi * 16;
                uint2 lo = *(const uint2*)&Ps[(rb + gid)     * 132 + kk + tig * 2];
                uint2 hi = *(const uint2*)&Ps[(rb + gid + 8) * 132 + kk + tig * 2];
                af[mi][0] = lo.x; af[mi][1] = hi.x; af[mi][2] = lo.y; af[mi][3] = hi.y;
            }
#pragma unroll
            for (int ni = 0; ni < 2; ni++) {
                int cb = wn * 16 + ni * 8;
                bf[ni][0] = Vs[(kk + tig)     * 68 + cb + gid];
                bf[ni][1] = Vs[(kk + tig + 4) * 68 + cb + gid];
            }
#pragma unroll
            for (int mi = 0; mi < 2; mi++)
#pragma unroll
                for (int ni = 0; ni < 2; ni++) mma8(acco[mi][ni], af[mi], bf[ni]);
        }
    }

    // rowsum -> 1/l (store for epilogue rescale)
    __syncthreads();
#pragma unroll
    for (int mi = 0; mi < 2; mi++)
#pragma unroll
        for (int hl = 0; hl < 2; hl++) {
            float v = lsum[mi][hl];
            v += __shfl_xor_sync(~0u, v, 1);
            v += __shfl_xor_sync(~0u, v, 2);
            if (tig == 0) red[wn * 128 + wm * 32 + mi * 16 + gid + hl * 8] = v;
        }
    __syncthreads();
    if (tid < 128) {
        float inv = 1.f / (red[tid] + red[128 + tid] + red[256 + tid] + red[384 + tid]);
        sm_inv[tid] = inv;
        g_linv[(size_t)bh * TQ + m0 + tid] = inv;
    }
    __syncthreads();

    // O normalize -> g_x
#pragma unroll
    for (int mi = 0; mi < 2; mi++)
#pragma unroll
        for (int hl = 0; hl < 2; hl++) {
            int row = wm * 32 + mi * 16 + gid + hl * 8;
            float inv = sm_inv[row];
#pragma unroll
            for (int ni = 0; ni < 2; ni++) {
                int c = wn * 16 + ni * 8 + tig * 2;
                *(float2*)&g_x[((size_t)bh * TQ + m0 + row) * DH + c] =
                    make_float2(acco[mi][ni][hl * 2] * inv,
                                acco[mi][ni][hl * 2 + 1] * inv);
            }
        }
}

// ---------------------------------------------------------------------------
extern "C" void kernel_launch(void* const* d_in, const int* in_sizes, int n_in,
                              void* d_out, int out_size)
{
    const float* query = (const float*)d_in[0];
    const float* key   = (const float*)d_in[1];
    const float* value = (const float*)d_in[2];
    const unsigned char* mask = (const unsigned char*)d_in[3];
    const float* Wq = (const float*)d_in[4];
    const float* bq = (const float*)d_in[5];
    const float* Wk = (const float*)d_in[6];
    const float* bk = (const float*)d_in[7];
    const float* Wv = (const float*)d_in[8];
    const float* bv = (const float*)d_in[9];
    const float* Wo = (const float*)d_in[10];
    const float* bo = (const float*)d_in[11];

    float* out_x = (float*)d_out;                       // [2048,4,1024]
    float* attn  = out_x + (size_t)TQ * BSZ * CDIM;     // [64,2048,2048]

    cudaFuncSetAttribute(attn_fused_kernel,
                         cudaFuncAttributeMaxDynamicSharedMemorySize, AT_SMEM);
    cudaFuncSetAttribute(qkv_proj_kernel,
                         cudaFuncAttributeMaxDynamicSharedMemorySize, PROJ_SMEM);
    cudaFuncSetAttribute(epilogue_kernel,
                         cudaFuncAttributeMaxDynamicSharedMemorySize, PROJ_SMEM);

    qkv_proj_kernel<<<dim3(8, 64, 3), 256, PROJ_SMEM>>>(query, key, value,
                                                        Wq, Wk, Wv, bq, bk, bv);
    attn_fused_kernel<<<dim3(16, 64), 512, AT_SMEM>>>(mask, attn);
    // 512 out_proj tiles interleaved 1:32 with 16384 rescale blocks
    epilogue_kernel<<<dim3(512 * 33), 256, PROJ_SMEM>>>(Wo, bo, out_x, attn);
}